// round 1
// baseline (speedup 1.0000x reference)
#include <cuda_runtime.h>
#include <math.h>

#define Bdim 128
#define Sdim 128
#define Ddim 256
#define Hdim 8
#define HDim 32
#define Fdim 2048
#define Ldim 4
#define BHdim (Bdim*Hdim)     /* 1024 */
#define NR (Bdim*Sdim)        /* 16384 rows */

// ---------------- scratch (device globals; no allocation allowed) ----------
__device__ float g_x[NR*Ddim];
__device__ float g_q[NR*Ddim];
__device__ float g_k[NR*Ddim];
__device__ float g_v[NR*Ddim];
__device__ float g_ctx[NR*Ddim];
__device__ float g_tmp[NR*Ddim];
__device__ float g_eb[(size_t)BHdim*Sdim*Sdim];   // [bh][j][i]
__device__ float g_at[(size_t)BHdim*Sdim*Sdim];   // [bh][i][j]
__device__ float g_ff[(size_t)NR*Fdim];

// ---------------- generic SGEMM: C[M,N] = A[M,K] @ W[K,N] + bias (opt relu) -
template<bool RELU>
__global__ __launch_bounds__(256, 2) void sgemm_kernel(
    const float* __restrict__ A, const float* __restrict__ W,
    const float* __restrict__ bias, float* __restrict__ C,
    int M, int N, int K)
{
    __shared__ float As[8][128];
    __shared__ float Ws[8][128];
    const int tid = threadIdx.x;
    const int bx = blockIdx.x, by = blockIdx.y;
    const int ty = tid >> 4, tx = tid & 15;
    const int aRow = tid >> 1, aCol = (tid & 1) << 2;
    const int wRow = tid >> 5, wCol = (tid & 31) << 2;
    const float* Ap = A + (size_t)(by * 128 + aRow) * K + aCol;
    const float* Wp = W + (size_t)wRow * N + bx * 128 + wCol;
    float acc[8][8];
#pragma unroll
    for (int i = 0; i < 8; i++)
#pragma unroll
        for (int j = 0; j < 8; j++) acc[i][j] = 0.f;

    for (int k0 = 0; k0 < K; k0 += 8) {
        float4 av = *(const float4*)(Ap + k0);
        float4 wv = *(const float4*)(Wp + (size_t)k0 * N);
        As[aCol + 0][aRow] = av.x;
        As[aCol + 1][aRow] = av.y;
        As[aCol + 2][aRow] = av.z;
        As[aCol + 3][aRow] = av.w;
        *(float4*)&Ws[wRow][wCol] = wv;
        __syncthreads();
#pragma unroll
        for (int kk = 0; kk < 8; kk++) {
            float af[8], wf[8];
            *(float4*)&af[0] = *(const float4*)&As[kk][ty * 8];
            *(float4*)&af[4] = *(const float4*)&As[kk][ty * 8 + 4];
            *(float4*)&wf[0] = *(const float4*)&Ws[kk][tx * 8];
            *(float4*)&wf[4] = *(const float4*)&Ws[kk][tx * 8 + 4];
#pragma unroll
            for (int i = 0; i < 8; i++)
#pragma unroll
                for (int j = 0; j < 8; j++)
                    acc[i][j] += af[i] * wf[j];
        }
        __syncthreads();
    }
    const int row0 = by * 128 + ty * 8;
    const int col0 = bx * 128 + tx * 8;
    float bv[8];
#pragma unroll
    for (int j = 0; j < 8; j++) bv[j] = bias[col0 + j];
#pragma unroll
    for (int i = 0; i < 8; i++) {
        float outv[8];
#pragma unroll
        for (int j = 0; j < 8; j++) {
            float t = acc[i][j] + bv[j];
            if (RELU) t = fmaxf(t, 0.f);
            outv[j] = t;
        }
        *(float4*)(C + (size_t)(row0 + i) * N + col0)     = *(float4*)&outv[0];
        *(float4*)(C + (size_t)(row0 + i) * N + col0 + 4) = *(float4*)&outv[4];
    }
}

// -------- edge-key bias: eb[bh][j][i] = sum_d ek[j,i,d] * q[bh,j,d] --------
// grid: (j = Sdim, bh_chunk = BH/128). Per block: [128 bh] x [128 i] x K=32.
__global__ __launch_bounds__(256) void ebias_kernel(
    const float* __restrict__ q, const float* __restrict__ ek,
    float* __restrict__ eb)
{
    const int j   = blockIdx.x;
    const int bh0 = blockIdx.y * 128;
    __shared__ float Qs[32][132];  // [d][bh_local]
    __shared__ float Es[32][132];  // [d][i]
    const int tid = threadIdx.x;
    {
        const int r = tid >> 1;           // 0..127
        const int half = tid & 1;         // d base = half*16
        const int bh = bh0 + r;
        const int b = bh >> 3, h = bh & 7;
        const float* qp = q  + (size_t)(b * Sdim + j) * Ddim + h * HDim + half * 16;
        const float* ep = ek + (size_t)(j * Sdim + r) * HDim + half * 16;
#pragma unroll
        for (int c = 0; c < 4; c++) {
            float4 vq = *(const float4*)(qp + c * 4);
            float4 ve = *(const float4*)(ep + c * 4);
            int d = half * 16 + c * 4;
            Qs[d+0][r] = vq.x; Qs[d+1][r] = vq.y; Qs[d+2][r] = vq.z; Qs[d+3][r] = vq.w;
            Es[d+0][r] = ve.x; Es[d+1][r] = ve.y; Es[d+2][r] = ve.z; Es[d+3][r] = ve.w;
        }
    }
    __syncthreads();
    const int ty = tid >> 4, tx = tid & 15;  // ty -> bh rows, tx -> i cols
    float acc[8][8];
#pragma unroll
    for (int i = 0; i < 8; i++)
#pragma unroll
        for (int c = 0; c < 8; c++) acc[i][c] = 0.f;
#pragma unroll
    for (int d = 0; d < 32; d++) {
        float af[8], bf[8];
        *(float4*)&af[0] = *(const float4*)&Qs[d][ty * 8];
        *(float4*)&af[4] = *(const float4*)&Qs[d][ty * 8 + 4];
        *(float4*)&bf[0] = *(const float4*)&Es[d][tx * 8];
        *(float4*)&bf[4] = *(const float4*)&Es[d][tx * 8 + 4];
#pragma unroll
        for (int i = 0; i < 8; i++)
#pragma unroll
            for (int c = 0; c < 8; c++) acc[i][c] += af[i] * bf[c];
    }
#pragma unroll
    for (int i = 0; i < 8; i++) {
        float* op = eb + ((size_t)(bh0 + ty * 8 + i) * Sdim + j) * Sdim + tx * 8;
        *(float4*)(op)     = *(float4*)&acc[i][0];
        *(float4*)(op + 4) = *(float4*)&acc[i][4];
    }
}

// -------- attention per (b,h): scores, bias add, mask, softmax, P@V --------
#define ATT_FLOATS (2*32*132 + 128*32 + 128*129)
#define ATT_BYTES  (ATT_FLOATS * 4)
__global__ __launch_bounds__(256) void attn_kernel(
    const float* __restrict__ q, const float* __restrict__ k,
    const float* __restrict__ v, const float* __restrict__ eb,
    const unsigned char* __restrict__ mask,
    float* __restrict__ attn_out, float* __restrict__ ctx)
{
    extern __shared__ float sm[];
    float (*Qs)[132] = (float(*)[132])sm;
    float (*Ks)[132] = (float(*)[132])(sm + 32 * 132);
    float (*Vs)[32]  = (float(*)[32]) (sm + 2 * 32 * 132);
    float (*Sc)[129] = (float(*)[129])(sm + 2 * 32 * 132 + 128 * 32);
    const int bh = blockIdx.x;
    const int b = bh >> 3, h = bh & 7;
    const int tid = threadIdx.x;

    // phase A: load q/k transposed [d][row], v natural [row][d], bias into Sc
    {
        const int r = tid >> 1;
        const int half = tid & 1;
        const float* qp = q + (size_t)(b * Sdim + r) * Ddim + h * HDim + half * 16;
        const float* kp = k + (size_t)(b * Sdim + r) * Ddim + h * HDim + half * 16;
        const float* vp = v + (size_t)(b * Sdim + r) * Ddim + h * HDim + half * 16;
#pragma unroll
        for (int c = 0; c < 4; c++) {
            int d = half * 16 + c * 4;
            float4 vq = *(const float4*)(qp + c * 4);
            float4 vk = *(const float4*)(kp + c * 4);
            Qs[d+0][r] = vq.x; Qs[d+1][r] = vq.y; Qs[d+2][r] = vq.z; Qs[d+3][r] = vq.w;
            Ks[d+0][r] = vk.x; Ks[d+1][r] = vk.y; Ks[d+2][r] = vk.z; Ks[d+3][r] = vk.w;
            *(float4*)&Vs[r][d] = *(const float4*)(vp + c * 4);
        }
        const int warp = tid >> 5, lane = tid & 31;
        for (int jj = warp; jj < Sdim; jj += 8) {
            float4 t = *(const float4*)(eb + ((size_t)bh * Sdim + jj) * Sdim + lane * 4);
            Sc[lane*4+0][jj] = t.x; Sc[lane*4+1][jj] = t.y;
            Sc[lane*4+2][jj] = t.z; Sc[lane*4+3][jj] = t.w;
        }
    }
    __syncthreads();

    // phase B: scores = (q@k^T + bias)*scale + mask
    const int ty = tid >> 4, tx = tid & 15;
    const int i0 = ty * 8, j0 = tx * 8;
    float acc[8][8];
#pragma unroll
    for (int i = 0; i < 8; i++)
#pragma unroll
        for (int j = 0; j < 8; j++) acc[i][j] = 0.f;
#pragma unroll
    for (int d = 0; d < 32; d++) {
        float af[8], bf[8];
        *(float4*)&af[0] = *(const float4*)&Qs[d][i0];
        *(float4*)&af[4] = *(const float4*)&Qs[d][i0 + 4];
        *(float4*)&bf[0] = *(const float4*)&Ks[d][j0];
        *(float4*)&bf[4] = *(const float4*)&Ks[d][j0 + 4];
#pragma unroll
        for (int i = 0; i < 8; i++)
#pragma unroll
            for (int j = 0; j < 8; j++) acc[i][j] += af[i] * bf[j];
    }
    const float scale = 0.17677669529663687f; // 32^-0.5
    const float NEGINF = -__int_as_float(0x7f800000);
#pragma unroll
    for (int ii = 0; ii < 8; ii++) {
        unsigned long long mv =
            *(const unsigned long long*)(mask + ((size_t)bh * Sdim + i0 + ii) * Sdim + j0);
#pragma unroll
        for (int jj = 0; jj < 8; jj++) {
            float s = (acc[ii][jj] + Sc[i0 + ii][j0 + jj]) * scale;
            if ((mv >> (8 * jj)) & 0xffULL) s = NEGINF;
            Sc[i0 + ii][j0 + jj] = s;
        }
    }
    __syncthreads();

    // phase C: row softmax; write probs to smem and to global attn
    {
        const int warp = tid >> 5, lane = tid & 31;
        for (int r = warp; r < Sdim; r += 8) {
            float vals[4];
#pragma unroll
            for (int c = 0; c < 4; c++) vals[c] = Sc[r][lane + 32 * c];
            float m = fmaxf(fmaxf(vals[0], vals[1]), fmaxf(vals[2], vals[3]));
#pragma unroll
            for (int o = 16; o > 0; o >>= 1) m = fmaxf(m, __shfl_xor_sync(0xffffffffu, m, o));
            float ssum = 0.f;
#pragma unroll
            for (int c = 0; c < 4; c++) { vals[c] = __expf(vals[c] - m); ssum += vals[c]; }
#pragma unroll
            for (int o = 16; o > 0; o >>= 1) ssum += __shfl_xor_sync(0xffffffffu, ssum, o);
            float inv = 1.f / ssum;
            float* ap = attn_out + ((size_t)bh * Sdim + r) * Sdim;
#pragma unroll
            for (int c = 0; c < 4; c++) {
                float p = vals[c] * inv;
                Sc[r][lane + 32 * c] = p;
                ap[lane + 32 * c] = p;
            }
        }
    }
    __syncthreads();

    // phase D: ctx[i][d] = sum_j P[i][j] * V[j][d]
    const int ig = tid >> 3;   // i base = ig*4
    const int dg = tid & 7;    // d base = dg*4
    float o[4][4];
#pragma unroll
    for (int c = 0; c < 4; c++)
#pragma unroll
        for (int e = 0; e < 4; e++) o[c][e] = 0.f;
    for (int j = 0; j < Sdim; j++) {
        float4 vv = *(const float4*)&Vs[j][dg * 4];
#pragma unroll
        for (int c = 0; c < 4; c++) {
            float p = Sc[ig * 4 + c][j];
            o[c][0] += p * vv.x; o[c][1] += p * vv.y;
            o[c][2] += p * vv.z; o[c][3] += p * vv.w;
        }
    }
#pragma unroll
    for (int c = 0; c < 4; c++) {
        float* cp = ctx + (size_t)(b * Sdim + ig * 4 + c) * Ddim + h * HDim + dg * 4;
        *(float4*)cp = make_float4(o[c][0], o[c][1], o[c][2], o[c][3]);
    }
}

// -------- edge-value: ctx[bh,i,d] += sum_j attn[bh,i,j] * ev[i,j,d] --------
// grid: (i = Sdim, bh_chunk = BH/128)
#define EV_FLOATS (128*132 + 128*32)
#define EV_BYTES  (EV_FLOATS * 4)
__global__ __launch_bounds__(256) void ev_kernel(
    const float* __restrict__ attn, const float* __restrict__ ev,
    float* __restrict__ ctx)
{
    const int i   = blockIdx.x;
    const int bh0 = blockIdx.y * 128;
    extern __shared__ float sm2[];
    float (*As)[132]  = (float(*)[132])sm2;             // [bh_local][j]
    float (*Evs)[32]  = (float(*)[32])(sm2 + 128 * 132);// [j][d]
    const int tid = threadIdx.x;
    {
        const int warp = tid >> 5, lane = tid & 31;
        for (int r = warp; r < 128; r += 8) {
            const float* p = attn + ((size_t)(bh0 + r) * Sdim + i) * Sdim + lane * 4;
            *(float4*)&As[r][lane * 4] = *(const float4*)p;
        }
        const int r2 = tid >> 1, half = tid & 1;
        const float* ep = ev + (size_t)(i * Sdim + r2) * HDim + half * 16;
#pragma unroll
        for (int c = 0; c < 4; c++)
            *(float4*)&Evs[r2][half * 16 + c * 4] = *(const float4*)(ep + c * 4);
    }
    __syncthreads();
    const int tg = tid >> 3;  // bh rows tg*4..
    const int dg = tid & 7;   // d cols dg*4..
    float o[4][4];
#pragma unroll
    for (int c = 0; c < 4; c++)
#pragma unroll
        for (int e = 0; e < 4; e++) o[c][e] = 0.f;
    for (int j = 0; j < Sdim; j++) {
        float4 bv = *(const float4*)&Evs[j][dg * 4];
#pragma unroll
        for (int c = 0; c < 4; c++) {
            float a = As[tg * 4 + c][j];
            o[c][0] += a * bv.x; o[c][1] += a * bv.y;
            o[c][2] += a * bv.z; o[c][3] += a * bv.w;
        }
    }
#pragma unroll
    for (int c = 0; c < 4; c++) {
        const int bh = bh0 + tg * 4 + c;
        const int b = bh >> 3, h = bh & 7;
        float* cp = ctx + (size_t)(b * Sdim + i) * Ddim + h * HDim + dg * 4;
        float4 cur = *(const float4*)cp;
        cur.x += o[c][0]; cur.y += o[c][1]; cur.z += o[c][2]; cur.w += o[c][3];
        *(float4*)cp = cur;
    }
}

// ---------------- layer norm: out = LN(alpha*in1 + in2) * g + b ------------
__global__ __launch_bounds__(256) void ln_kernel(
    const float* __restrict__ in1, const float* __restrict__ in2, float alpha,
    const float* __restrict__ g, const float* __restrict__ b,
    float* __restrict__ out)
{
    const int warp = threadIdx.x >> 5, lane = threadIdx.x & 31;
    const int row = blockIdx.x * 8 + warp;
    const float* p1 = in1 + (size_t)row * Ddim;
    float v[8];
#pragma unroll
    for (int c = 0; c < 8; c++) {
        int col = lane + 32 * c;
        float t = alpha * p1[col];
        if (in2) t += in2[(size_t)row * Ddim + col];
        v[c] = t;
    }
    float s = 0.f;
#pragma unroll
    for (int c = 0; c < 8; c++) s += v[c];
#pragma unroll
    for (int o = 16; o > 0; o >>= 1) s += __shfl_xor_sync(0xffffffffu, s, o);
    float mu = s * (1.f / Ddim);
    float var = 0.f;
#pragma unroll
    for (int c = 0; c < 8; c++) { float d = v[c] - mu; var += d * d; }
#pragma unroll
    for (int o = 16; o > 0; o >>= 1) var += __shfl_xor_sync(0xffffffffu, var, o);
    var *= (1.f / Ddim);
    float inv = rsqrtf(var + 1e-5f);
#pragma unroll
    for (int c = 0; c < 8; c++) {
        int col = lane + 32 * c;
        out[(size_t)row * Ddim + col] = (v[c] - mu) * inv * g[col] + b[col];
    }
}

// ---------------- misc -----------------------------------------------------
__global__ void copy_kernel(const float* __restrict__ src, float* __restrict__ dst)
{
    size_t idx = (size_t)blockIdx.x * 256 + threadIdx.x;
    dst[idx] = src[idx];
}

__global__ void out_transpose(const float* __restrict__ x, float* __restrict__ out)
{
    size_t idx = (size_t)blockIdx.x * 256 + threadIdx.x;  // over S*B*D, [s][b][d]
    int d = (int)(idx % Ddim);
    size_t sb = idx / Ddim;
    int bcol = (int)(sb % Bdim);
    int s = (int)(sb / Bdim);
    out[idx] = x[((size_t)bcol * Sdim + s) * Ddim + d];
}

// ---------------- host -----------------------------------------------------
extern "C" void kernel_launch(void* const* d_in, const int* in_sizes, int n_in,
                              void* d_out, int out_size)
{
    const float* facts = (const float*)d_in[0];
    const float* ekey  = (const float*)d_in[1];
    const float* evalp = (const float*)d_in[2];
    const unsigned char* mask = (const unsigned char*)d_in[3];
    const float *Wq, *Wk, *Wv, *Wo, *bq, *bk, *bv, *bo;
    if (in_sizes[5] == Ldim * Ddim) {
        // signature order: Wq,bq,Wk,bk,Wv,bv,Wo,bo
        Wq = (const float*)d_in[4];  bq = (const float*)d_in[5];
        Wk = (const float*)d_in[6];  bk = (const float*)d_in[7];
        Wv = (const float*)d_in[8];  bv = (const float*)d_in[9];
        Wo = (const float*)d_in[10]; bo = (const float*)d_in[11];
    } else {
        // dict insertion order: Wq,Wk,Wv,Wo,bq,bk,bv,bo
        Wq = (const float*)d_in[4];  Wk = (const float*)d_in[5];
        Wv = (const float*)d_in[6];  Wo = (const float*)d_in[7];
        bq = (const float*)d_in[8];  bk = (const float*)d_in[9];
        bv = (const float*)d_in[10]; bo = (const float*)d_in[11];
    }
    const float* ln1g = (const float*)d_in[12];
    const float* ln1b = (const float*)d_in[13];
    const float* W1   = (const float*)d_in[14];
    const float* b1   = (const float*)d_in[15];
    const float* W2   = (const float*)d_in[16];
    const float* b2   = (const float*)d_in[17];
    const float* ln2g = (const float*)d_in[18];
    const float* ln2b = (const float*)d_in[19];

    float *x, *q, *k, *v, *ctx, *tmp, *eb, *at, *ff;
    cudaGetSymbolAddress((void**)&x,   g_x);
    cudaGetSymbolAddress((void**)&q,   g_q);
    cudaGetSymbolAddress((void**)&k,   g_k);
    cudaGetSymbolAddress((void**)&v,   g_v);
    cudaGetSymbolAddress((void**)&ctx, g_ctx);
    cudaGetSymbolAddress((void**)&tmp, g_tmp);
    cudaGetSymbolAddress((void**)&eb,  g_eb);
    cudaGetSymbolAddress((void**)&at,  g_at);
    cudaGetSymbolAddress((void**)&ff,  g_ff);

    cudaFuncSetAttribute(attn_kernel, cudaFuncAttributeMaxDynamicSharedMemorySize, ATT_BYTES);
    cudaFuncSetAttribute(ev_kernel,   cudaFuncAttributeMaxDynamicSharedMemorySize, EV_BYTES);

    copy_kernel<<<NR * Ddim / 256, 256>>>(facts, x);

    for (int l = 0; l < Ldim; l++) {
        const size_t wo = (size_t)l * Ddim * Ddim;
        sgemm_kernel<false><<<dim3(Ddim / 128, NR / 128), 256>>>(
            x, Wq + wo, bq + l * Ddim, q, NR, Ddim, Ddim);
        sgemm_kernel<false><<<dim3(Ddim / 128, NR / 128), 256>>>(
            x, Wk + wo, bk + l * Ddim, k, NR, Ddim, Ddim);
        sgemm_kernel<false><<<dim3(Ddim / 128, NR / 128), 256>>>(
            x, Wv + wo, bv + l * Ddim, v, NR, Ddim, Ddim);

        ebias_kernel<<<dim3(Sdim, BHdim / 128), 256>>>(q, ekey, eb);
        attn_kernel<<<BHdim, 256, ATT_BYTES>>>(q, k, v, eb, mask, at, ctx);
        ev_kernel<<<dim3(Sdim, BHdim / 128), 256, EV_BYTES>>>(at, evalp, ctx);

        sgemm_kernel<false><<<dim3(Ddim / 128, NR / 128), 256>>>(
            ctx, Wo + wo, bo + l * Ddim, tmp, NR, Ddim, Ddim);
        ln_kernel<<<NR / 8, 256>>>(tmp, x, 1.f, ln1g + l * Ddim, ln1b + l * Ddim, x);

        sgemm_kernel<true><<<dim3(Fdim / 128, NR / 128), 256>>>(
            x, W1 + (size_t)l * Ddim * Fdim, b1 + l * Fdim, ff, NR, Fdim, Ddim);
        sgemm_kernel<false><<<dim3(Ddim / 128, NR / 128), 256>>>(
            ff, W2 + (size_t)l * Fdim * Ddim, b2 + l * Ddim, tmp, NR, Ddim, Fdim);
        ln_kernel<<<NR / 8, 256>>>(tmp, nullptr, 2.f, ln2g + l * Ddim, ln2b + l * Ddim, x);
    }

    out_transpose<<<NR * Ddim / 256, 256>>>(x, (float*)d_out);
}

// round 3
// speedup vs baseline: 1.8212x; 1.8212x over previous
#include <cuda_runtime.h>
#include <cstdint>
#include <math.h>

#define Bdim 128
#define Sdim 128
#define Ddim 256
#define Hdim 8
#define HDim 32
#define Fdim 2048
#define Ldim 4
#define BHdim (Bdim*Hdim)     /* 1024 */
#define NR (Bdim*Sdim)        /* 16384 rows */
#define QKVS 768              /* fused qkv row stride */

// ---------------- scratch (device globals; no allocation allowed) ----------
__device__ float g_x[NR*Ddim];
__device__ float g_qkv[(size_t)NR*QKVS];
__device__ float g_ctx[NR*Ddim];
__device__ float g_tmp[NR*Ddim];
__device__ float g_eb[(size_t)BHdim*Sdim*Sdim];   // [bh][j][i]
__device__ float g_at[(size_t)BHdim*Sdim*Sdim];   // [bh][i][j]
__device__ float g_ff[(size_t)NR*Fdim];
// transposed weights [N][K] layouts
__device__ float g_wqkvT[(size_t)Ldim*3*Ddim*Ddim];  // per layer: [768][256]
__device__ float g_woT[(size_t)Ldim*Ddim*Ddim];      // [256][256]
__device__ float g_w1T[(size_t)Ldim*Fdim*Ddim];      // [2048][256]
__device__ float g_w2T[(size_t)Ldim*Ddim*Fdim];      // [256][2048]
__device__ float g_bqkv[Ldim*QKVS];

__device__ __forceinline__ float to_tf32(float x) {
    float y;
    asm("cvt.rna.tf32.f32 %0, %1;" : "=f"(y) : "f"(x));
    return y;
}

// ==================== mma.sync tf32 GEMM ===================================
// C[M,N] = A[M,K] @ BT[N,K]^T + bias, optional relu.
// CTA tile 128x128, 8 warps (4m x 2n), warp tile 32x64, K-chunk 32.
#define CH 32
#define PADK 36
#define GSM_FLOATS (4 * 128 * PADK)     /* 2 bufs x (A+B) */
#define GSM_BYTES  (GSM_FLOATS * 4)     /* 73728 */

__device__ __forceinline__ void mma_tf32(
    float& c0, float& c1, float& c2, float& c3,
    uint32_t a0, uint32_t a1, uint32_t a2, uint32_t a3,
    uint32_t b0, uint32_t b1)
{
    asm volatile(
        "mma.sync.aligned.m16n8k8.row.col.f32.tf32.tf32.f32 "
        "{%0,%1,%2,%3}, {%4,%5,%6,%7}, {%8,%9}, {%0,%1,%2,%3};"
        : "+f"(c0), "+f"(c1), "+f"(c2), "+f"(c3)
        : "r"(a0), "r"(a1), "r"(a2), "r"(a3), "r"(b0), "r"(b1));
}

template<bool RELU>
__global__ __launch_bounds__(256) void mma_gemm(
    const float* __restrict__ A, const float* __restrict__ BT,
    const float* __restrict__ bias, float* __restrict__ C,
    int M, int N, int K)
{
    extern __shared__ float sm[];
    float* Asm[2] = { sm,                sm + 128 * PADK };
    float* Bsm[2] = { sm + 2*128*PADK,   sm + 3*128*PADK };
    const int tid = threadIdx.x;
    const int lane = tid & 31, wid = tid >> 5;
    const int wm = (wid >> 1) * 32, wn = (wid & 1) * 64;
    const int m0 = blockIdx.y * 128, n0 = blockIdx.x * 128;
    const float* Abase = A + (size_t)m0 * K;
    const float* Bbase = BT + (size_t)n0 * K;
    const int nch = K / CH;

    const int srow = tid >> 3;          // 0..31 base rows (x4 iters -> 128)
    const int sc4  = tid & 7;           // float4 column within 32-k chunk

    float4 ra[4], rb[4];
    auto ldg = [&](int c) {
        const float* Ap = Abase + c * CH;
        const float* Bp = Bbase + c * CH;
#pragma unroll
        for (int it = 0; it < 4; ++it) {
            int row = srow + it * 32;
            ra[it] = *(const float4*)(Ap + (size_t)row * K + sc4 * 4);
            rb[it] = *(const float4*)(Bp + (size_t)row * K + sc4 * 4);
        }
    };
    auto sts = [&](int buf) {
#pragma unroll
        for (int it = 0; it < 4; ++it) {
            int row = srow + it * 32;
            float4 va = ra[it], vb = rb[it];
            va.x = to_tf32(va.x); va.y = to_tf32(va.y);
            va.z = to_tf32(va.z); va.w = to_tf32(va.w);
            vb.x = to_tf32(vb.x); vb.y = to_tf32(vb.y);
            vb.z = to_tf32(vb.z); vb.w = to_tf32(vb.w);
            *(float4*)&Asm[buf][row * PADK + sc4 * 4] = va;
            *(float4*)&Bsm[buf][row * PADK + sc4 * 4] = vb;
        }
    };

    float acc[2][8][4];
#pragma unroll
    for (int mt = 0; mt < 2; ++mt)
#pragma unroll
        for (int nt = 0; nt < 8; ++nt)
#pragma unroll
            for (int e = 0; e < 4; ++e) acc[mt][nt][e] = 0.f;

    const int qr = lane >> 2;   // group id 0..7
    const int qc = lane & 3;    // thread-in-group 0..3

    ldg(0);
    sts(0);
    __syncthreads();

    for (int c = 0; c < nch; ++c) {
        if (c + 1 < nch) ldg(c + 1);
        const int buf = c & 1;
        const float* Ab = Asm[buf];
        const float* Bb = Bsm[buf];
#pragma unroll
        for (int kk = 0; kk < 4; ++kk) {
            const int kb = kk * 8;
            uint32_t a[2][4];
#pragma unroll
            for (int mt = 0; mt < 2; ++mt) {
                const int r = wm + mt * 16 + qr;
                a[mt][0] = __float_as_uint(Ab[(r    ) * PADK + kb + qc]);
                a[mt][1] = __float_as_uint(Ab[(r + 8) * PADK + kb + qc]);
                a[mt][2] = __float_as_uint(Ab[(r    ) * PADK + kb + 4 + qc]);
                a[mt][3] = __float_as_uint(Ab[(r + 8) * PADK + kb + 4 + qc]);
            }
#pragma unroll
            for (int nt = 0; nt < 8; ++nt) {
                const int n = wn + nt * 8 + qr;
                uint32_t b0 = __float_as_uint(Bb[n * PADK + kb + qc]);
                uint32_t b1 = __float_as_uint(Bb[n * PADK + kb + 4 + qc]);
#pragma unroll
                for (int mt = 0; mt < 2; ++mt)
                    mma_tf32(acc[mt][nt][0], acc[mt][nt][1],
                             acc[mt][nt][2], acc[mt][nt][3],
                             a[mt][0], a[mt][1], a[mt][2], a[mt][3], b0, b1);
            }
        }
        if (c + 1 < nch) {
            __syncthreads();     // all warps done reading buf (c+1)&1 (chunk c-1)
            sts((c + 1) & 1);
            __syncthreads();
        }
    }

    // epilogue
#pragma unroll
    for (int mt = 0; mt < 2; ++mt) {
        const int r = m0 + wm + mt * 16 + qr;
#pragma unroll
        for (int nt = 0; nt < 8; ++nt) {
            const int col = n0 + wn + nt * 8 + qc * 2;
            float b0 = bias[col], b1 = bias[col + 1];
            float2 v0, v1;
            v0.x = acc[mt][nt][0] + b0; v0.y = acc[mt][nt][1] + b1;
            v1.x = acc[mt][nt][2] + b0; v1.y = acc[mt][nt][3] + b1;
            if (RELU) {
                v0.x = fmaxf(v0.x, 0.f); v0.y = fmaxf(v0.y, 0.f);
                v1.x = fmaxf(v1.x, 0.f); v1.y = fmaxf(v1.y, 0.f);
            }
            *(float2*)(C + (size_t)r * N + col)       = v0;
            *(float2*)(C + (size_t)(r + 8) * N + col) = v1;
        }
    }
}

// ==================== weight transpose: WT[n][k] = W[k][n] =================
__global__ __launch_bounds__(256) void transpose_kernel(
    const float* __restrict__ W, float* __restrict__ WT,
    int K, int N, size_t sstride, size_t dstride)
{
    __shared__ float t[32][33];
    const float* Wl = W + blockIdx.z * sstride;
    float* WTl = WT + blockIdx.z * dstride;
    const int kx = blockIdx.y * 32, nx = blockIdx.x * 32;
    const int x = threadIdx.x & 31, y = threadIdx.x >> 5;
#pragma unroll
    for (int yy = y; yy < 32; yy += 8)
        t[yy][x] = Wl[(size_t)(kx + yy) * N + nx + x];
    __syncthreads();
#pragma unroll
    for (int yy = y; yy < 32; yy += 8)
        WTl[(size_t)(nx + yy) * K + kx + x] = t[x][yy];
}

__global__ void pack_bqkv(const float* bq, const float* bk, const float* bv, float* out)
{
    int idx = blockIdx.x * 256 + threadIdx.x;  // over L*768
    if (idx >= Ldim * QKVS) return;
    int l = idx / QKVS, j = idx % QKVS;
    float v;
    if (j < 256)      v = bq[l * 256 + j];
    else if (j < 512) v = bk[l * 256 + j - 256];
    else              v = bv[l * 256 + j - 512];
    out[idx] = v;
}

// -------- edge-key bias: eb[bh][j][i] = sum_d ek[j,i,d] * q[bh,j,d] --------
__global__ __launch_bounds__(256) void ebias_kernel(
    const float* __restrict__ qkv, const float* __restrict__ ek,
    float* __restrict__ eb)
{
    const int j   = blockIdx.x;
    const int bh0 = blockIdx.y * 128;
    __shared__ float Qs[32][132];
    __shared__ float Es[32][132];
    const int tid = threadIdx.x;
    {
        const int r = tid >> 1;
        const int half = tid & 1;
        const int bh = bh0 + r;
        const int b = bh >> 3, h = bh & 7;
        const float* qp = qkv + (size_t)(b * Sdim + j) * QKVS + h * HDim + half * 16;
        const float* ep = ek + (size_t)(j * Sdim + r) * HDim + half * 16;
#pragma unroll
        for (int c = 0; c < 4; c++) {
            float4 vq = *(const float4*)(qp + c * 4);
            float4 ve = *(const float4*)(ep + c * 4);
            int d = half * 16 + c * 4;
            Qs[d+0][r] = vq.x; Qs[d+1][r] = vq.y; Qs[d+2][r] = vq.z; Qs[d+3][r] = vq.w;
            Es[d+0][r] = ve.x; Es[d+1][r] = ve.y; Es[d+2][r] = ve.z; Es[d+3][r] = ve.w;
        }
    }
    __syncthreads();
    const int ty = tid >> 4, tx = tid & 15;
    float acc[8][8];
#pragma unroll
    for (int i = 0; i < 8; i++)
#pragma unroll
        for (int c = 0; c < 8; c++) acc[i][c] = 0.f;
#pragma unroll
    for (int d = 0; d < 32; d++) {
        float af[8], bf[8];
        *(float4*)&af[0] = *(const float4*)&Qs[d][ty * 8];
        *(float4*)&af[4] = *(const float4*)&Qs[d][ty * 8 + 4];
        *(float4*)&bf[0] = *(const float4*)&Es[d][tx * 8];
        *(float4*)&bf[4] = *(const float4*)&Es[d][tx * 8 + 4];
#pragma unroll
        for (int i = 0; i < 8; i++)
#pragma unroll
            for (int c = 0; c < 8; c++) acc[i][c] += af[i] * bf[c];
    }
#pragma unroll
    for (int i = 0; i < 8; i++) {
        float* op = eb + ((size_t)(bh0 + ty * 8 + i) * Sdim + j) * Sdim + tx * 8;
        *(float4*)(op)     = *(float4*)&acc[i][0];
        *(float4*)(op + 4) = *(float4*)&acc[i][4];
    }
}

// -------- attention per (b,h) ---------------------------------------------
#define ATT_FLOATS (2*32*132 + 128*32 + 128*129)
#define ATT_BYTES  (ATT_FLOATS * 4)
__global__ __launch_bounds__(256) void attn_kernel(
    const float* __restrict__ qkv, const float* __restrict__ eb,
    const unsigned char* __restrict__ mask,
    float* __restrict__ attn_out, float* __restrict__ ctx)
{
    extern __shared__ float sm[];
    float (*Qs)[132] = (float(*)[132])sm;
    float (*Ks)[132] = (float(*)[132])(sm + 32 * 132);
    float (*Vs)[32]  = (float(*)[32]) (sm + 2 * 32 * 132);
    float (*Sc)[129] = (float(*)[129])(sm + 2 * 32 * 132 + 128 * 32);
    const int bh = blockIdx.x;
    const int b = bh >> 3, h = bh & 7;
    const int tid = threadIdx.x;

    {
        const int r = tid >> 1;
        const int half = tid & 1;
        const float* base = qkv + (size_t)(b * Sdim + r) * QKVS + h * HDim + half * 16;
        const float* qp = base;
        const float* kp = base + 256;
        const float* vp = base + 512;
#pragma unroll
        for (int c = 0; c < 4; c++) {
            int d = half * 16 + c * 4;
            float4 vq = *(const float4*)(qp + c * 4);
            float4 vk = *(const float4*)(kp + c * 4);
            Qs[d+0][r] = vq.x; Qs[d+1][r] = vq.y; Qs[d+2][r] = vq.z; Qs[d+3][r] = vq.w;
            Ks[d+0][r] = vk.x; Ks[d+1][r] = vk.y; Ks[d+2][r] = vk.z; Ks[d+3][r] = vk.w;
            *(float4*)&Vs[r][d] = *(const float4*)(vp + c * 4);
        }
        const int warp = tid >> 5, lane = tid & 31;
        for (int jj = warp; jj < Sdim; jj += 8) {
            float4 t = *(const float4*)(eb + ((size_t)bh * Sdim + jj) * Sdim + lane * 4);
            Sc[lane*4+0][jj] = t.x; Sc[lane*4+1][jj] = t.y;
            Sc[lane*4+2][jj] = t.z; Sc[lane*4+3][jj] = t.w;
        }
    }
    __syncthreads();

    const int ty = tid >> 4, tx = tid & 15;
    const int i0 = ty * 8, j0 = tx * 8;
    float acc[8][8];
#pragma unroll
    for (int i = 0; i < 8; i++)
#pragma unroll
        for (int j = 0; j < 8; j++) acc[i][j] = 0.f;
#pragma unroll
    for (int d = 0; d < 32; d++) {
        float af[8], bf[8];
        *(float4*)&af[0] = *(const float4*)&Qs[d][i0];
        *(float4*)&af[4] = *(const float4*)&Qs[d][i0 + 4];
        *(float4*)&bf[0] = *(const float4*)&Ks[d][j0];
        *(float4*)&bf[4] = *(const float4*)&Ks[d][j0 + 4];
#pragma unroll
        for (int i = 0; i < 8; i++)
#pragma unroll
            for (int j = 0; j < 8; j++) acc[i][j] += af[i] * bf[j];
    }
    const float scale = 0.17677669529663687f;
    const float NEGINF = -__int_as_float(0x7f800000);
#pragma unroll
    for (int ii = 0; ii < 8; ii++) {
        unsigned long long mv =
            *(const unsigned long long*)(mask + ((size_t)bh * Sdim + i0 + ii) * Sdim + j0);
#pragma unroll
        for (int jj = 0; jj < 8; jj++) {
            float s = (acc[ii][jj] + Sc[i0 + ii][j0 + jj]) * scale;
            if ((mv >> (8 * jj)) & 0xffULL) s = NEGINF;
            Sc[i0 + ii][j0 + jj] = s;
        }
    }
    __syncthreads();

    {
        const int warp = tid >> 5, lane = tid & 31;
        for (int r = warp; r < Sdim; r += 8) {
            float vals[4];
#pragma unroll
            for (int c = 0; c < 4; c++) vals[c] = Sc[r][lane + 32 * c];
            float m = fmaxf(fmaxf(vals[0], vals[1]), fmaxf(vals[2], vals[3]));
#pragma unroll
            for (int o = 16; o > 0; o >>= 1) m = fmaxf(m, __shfl_xor_sync(0xffffffffu, m, o));
            float ssum = 0.f;
#pragma unroll
            for (int c = 0; c < 4; c++) { vals[c] = __expf(vals[c] - m); ssum += vals[c]; }
#pragma unroll
            for (int o = 16; o > 0; o >>= 1) ssum += __shfl_xor_sync(0xffffffffu, ssum, o);
            float inv = 1.f / ssum;
            float* ap = attn_out + ((size_t)bh * Sdim + r) * Sdim;
#pragma unroll
            for (int c = 0; c < 4; c++) {
                float p = vals[c] * inv;
                Sc[r][lane + 32 * c] = p;
                ap[lane + 32 * c] = p;
            }
        }
    }
    __syncthreads();

    const int ig = tid >> 3;
    const int dg = tid & 7;
    float o[4][4];
#pragma unroll
    for (int c = 0; c < 4; c++)
#pragma unroll
        for (int e = 0; e < 4; e++) o[c][e] = 0.f;
    for (int j = 0; j < Sdim; j++) {
        float4 vv = *(const float4*)&Vs[j][dg * 4];
#pragma unroll
        for (int c = 0; c < 4; c++) {
            float p = Sc[ig * 4 + c][j];
            o[c][0] += p * vv.x; o[c][1] += p * vv.y;
            o[c][2] += p * vv.z; o[c][3] += p * vv.w;
        }
    }
#pragma unroll
    for (int c = 0; c < 4; c++) {
        float* cp = ctx + (size_t)(b * Sdim + ig * 4 + c) * Ddim + h * HDim + dg * 4;
        *(float4*)cp = make_float4(o[c][0], o[c][1], o[c][2], o[c][3]);
    }
}

// -------- edge-value: ctx[bh,i,d] += sum_j attn[bh,i,j] * ev[i,j,d] --------
#define EV_FLOATS (128*132 + 128*32)
#define EV_BYTES  (EV_FLOATS * 4)
__global__ __launch_bounds__(256) void ev_kernel(
    const float* __restrict__ attn, const float* __restrict__ ev,
    float* __restrict__ ctx)
{
    const int i   = blockIdx.x;
    const int bh0 = blockIdx.y * 128;
    extern __shared__ float sm2[];
    float (*As)[132]  = (float(*)[132])sm2;
    float (*Evs)[32]  = (float(*)[32])(sm2 + 128 * 132);
    const int tid = threadIdx.x;
    {
        const int warp = tid >> 5, lane = tid & 31;
        for (int r = warp; r < 128; r += 8) {
            const float* p = attn + ((size_t)(bh0 + r) * Sdim + i) * Sdim + lane * 4;
            *(float4*)&As[r][lane * 4] = *(const float4*)p;
        }
        const int r2 = tid >> 1, half = tid & 1;
        const float* ep = ev + (size_t)(i * Sdim + r2) * HDim + half * 16;
#pragma unroll
        for (int c = 0; c < 4; c++)
            *(float4*)&Evs[r2][half * 16 + c * 4] = *(const float4*)(ep + c * 4);
    }
    __syncthreads();
    const int tg = tid >> 3;
    const int dg = tid & 7;
    float o[4][4];
#pragma unroll
    for (int c = 0; c < 4; c++)
#pragma unroll
        for (int e = 0; e < 4; e++) o[c][e] = 0.f;
    for (int j = 0; j < Sdim; j++) {
        float4 bv = *(const float4*)&Evs[j][dg * 4];
#pragma unroll
        for (int c = 0; c < 4; c++) {
            float a = As[tg * 4 + c][j];
            o[c][0] += a * bv.x; o[c][1] += a * bv.y;
            o[c][2] += a * bv.z; o[c][3] += a * bv.w;
        }
    }
#pragma unroll
    for (int c = 0; c < 4; c++) {
        const int bh = bh0 + tg * 4 + c;
        const int b = bh >> 3, h = bh & 7;
        float* cp = ctx + (size_t)(b * Sdim + i) * Ddim + h * HDim + dg * 4;
        float4 cur = *(const float4*)cp;
        cur.x += o[c][0]; cur.y += o[c][1]; cur.z += o[c][2]; cur.w += o[c][3];
        *(float4*)cp = cur;
    }
}

// ---------------- layer norm ----------------------------------------------
__global__ __launch_bounds__(256) void ln_kernel(
    const float* __restrict__ in1, const float* __restrict__ in2, float alpha,
    const float* __restrict__ g, const float* __restrict__ b,
    float* __restrict__ out)
{
    const int warp = threadIdx.x >> 5, lane = threadIdx.x & 31;
    const int row = blockIdx.x * 8 + warp;
    const float* p1 = in1 + (size_t)row * Ddim;
    float v[8];
#pragma unroll
    for (int c = 0; c < 8; c++) {
        int col = lane + 32 * c;
        float t = alpha * p1[col];
        if (in2) t += in2[(size_t)row * Ddim + col];
        v[c] = t;
    }
    float s = 0.f;
#pragma unroll
    for (int c = 0; c < 8; c++) s += v[c];
#pragma unroll
    for (int o = 16; o > 0; o >>= 1) s += __shfl_xor_sync(0xffffffffu, s, o);
    float mu = s * (1.f / Ddim);
    float var = 0.f;
#pragma unroll
    for (int c = 0; c < 8; c++) { float d = v[c] - mu; var += d * d; }
#pragma unroll
    for (int o = 16; o > 0; o >>= 1) var += __shfl_xor_sync(0xffffffffu, var, o);
    var *= (1.f / Ddim);
    float inv = rsqrtf(var + 1e-5f);
#pragma unroll
    for (int c = 0; c < 8; c++) {
        int col = lane + 32 * c;
        out[(size_t)row * Ddim + col] = (v[c] - mu) * inv * g[col] + b[col];
    }
}

// ---------------- misc -----------------------------------------------------
__global__ void copy_kernel(const float* __restrict__ src, float* __restrict__ dst)
{
    size_t idx = (size_t)blockIdx.x * 256 + threadIdx.x;
    dst[idx] = src[idx];
}

__global__ void out_transpose(const float* __restrict__ x, float* __restrict__ out)
{
    size_t idx = (size_t)blockIdx.x * 256 + threadIdx.x;
    int d = (int)(idx % Ddim);
    size_t sb = idx / Ddim;
    int bcol = (int)(sb % Bdim);
    int s = (int)(sb / Bdim);
    out[idx] = x[((size_t)bcol * Sdim + s) * Ddim + d];
}

// ---------------- host -----------------------------------------------------
extern "C" void kernel_launch(void* const* d_in, const int* in_sizes, int n_in,
                              void* d_out, int out_size)
{
    const float* facts = (const float*)d_in[0];
    const float* ekey  = (const float*)d_in[1];
    const float* evalp = (const float*)d_in[2];
    const unsigned char* mask = (const unsigned char*)d_in[3];
    const float *Wq, *Wk, *Wv, *Wo, *bq, *bk, *bv, *bo;
    if (in_sizes[5] == Ldim * Ddim) {
        Wq = (const float*)d_in[4];  bq = (const float*)d_in[5];
        Wk = (const float*)d_in[6];  bk = (const float*)d_in[7];
        Wv = (const float*)d_in[8];  bv = (const float*)d_in[9];
        Wo = (const float*)d_in[10]; bo = (const float*)d_in[11];
    } else {
        Wq = (const float*)d_in[4];  Wk = (const float*)d_in[5];
        Wv = (const float*)d_in[6];  Wo = (const float*)d_in[7];
        bq = (const float*)d_in[8];  bk = (const float*)d_in[9];
        bv = (const float*)d_in[10]; bo = (const float*)d_in[11];
    }
    const float* ln1g = (const float*)d_in[12];
    const float* ln1b = (const float*)d_in[13];
    const float* W1   = (const float*)d_in[14];
    const float* b1   = (const float*)d_in[15];
    const float* W2   = (const float*)d_in[16];
    const float* b2   = (const float*)d_in[17];
    const float* ln2g = (const float*)d_in[18];
    const float* ln2b = (const float*)d_in[19];

    float *x, *qkv, *ctx, *tmp, *eb, *at, *ff;
    float *wqkvT, *woT, *w1T, *w2T, *bqkvp;
    cudaGetSymbolAddress((void**)&x,    g_x);
    cudaGetSymbolAddress((void**)&qkv,  g_qkv);
    cudaGetSymbolAddress((void**)&ctx,  g_ctx);
    cudaGetSymbolAddress((void**)&tmp,  g_tmp);
    cudaGetSymbolAddress((void**)&eb,   g_eb);
    cudaGetSymbolAddress((void**)&at,   g_at);
    cudaGetSymbolAddress((void**)&ff,   g_ff);
    cudaGetSymbolAddress((void**)&wqkvT, g_wqkvT);
    cudaGetSymbolAddress((void**)&woT,  g_woT);
    cudaGetSymbolAddress((void**)&w1T,  g_w1T);
    cudaGetSymbolAddress((void**)&w2T,  g_w2T);
    cudaGetSymbolAddress((void**)&bqkvp, g_bqkv);

    cudaFuncSetAttribute(mma_gemm<false>, cudaFuncAttributeMaxDynamicSharedMemorySize, GSM_BYTES);
    cudaFuncSetAttribute(mma_gemm<true>,  cudaFuncAttributeMaxDynamicSharedMemorySize, GSM_BYTES);
    cudaFuncSetAttribute(attn_kernel, cudaFuncAttributeMaxDynamicSharedMemorySize, ATT_BYTES);
    cudaFuncSetAttribute(ev_kernel,   cudaFuncAttributeMaxDynamicSharedMemorySize, EV_BYTES);

    // ---- weight transposes + bias pack (per replay; ~20us total) ----
    transpose_kernel<<<dim3(8, 8, Ldim), 256>>>(Wq, wqkvT + 0,      Ddim, Ddim,
        (size_t)Ddim*Ddim, (size_t)3*Ddim*Ddim);
    transpose_kernel<<<dim3(8, 8, Ldim), 256>>>(Wk, wqkvT + 65536,  Ddim, Ddim,
        (size_t)Ddim*Ddim, (size_t)3*Ddim*Ddim);
    transpose_kernel<<<dim3(8, 8, Ldim), 256>>>(Wv, wqkvT + 131072, Ddim, Ddim,
        (size_t)Ddim*Ddim, (size_t)3*Ddim*Ddim);
    transpose_kernel<<<dim3(8, 8, Ldim), 256>>>(Wo, woT, Ddim, Ddim,
        (size_t)Ddim*Ddim, (size_t)Ddim*Ddim);
    transpose_kernel<<<dim3(64, 8, Ldim), 256>>>(W1, w1T, Ddim, Fdim,
        (size_t)Ddim*Fdim, (size_t)Fdim*Ddim);
    transpose_kernel<<<dim3(8, 64, Ldim), 256>>>(W2, w2T, Fdim, Ddim,
        (size_t)Fdim*Ddim, (size_t)Ddim*Fdim);
    pack_bqkv<<<(Ldim*QKVS + 255)/256, 256>>>(bq, bk, bv, bqkvp);

    copy_kernel<<<NR * Ddim / 256, 256>>>(facts, x);

    for (int l = 0; l < Ldim; l++) {
        // fused qkv: C[16384,768] = x @ [Wq|Wk|Wv]
        mma_gemm<false><<<dim3(QKVS / 128, NR / 128), 256, GSM_BYTES>>>(
            x, wqkvT + (size_t)l * 3 * Ddim * Ddim, bqkvp + l * QKVS, qkv,
            NR, QKVS, Ddim);

        ebias_kernel<<<dim3(Sdim, BHdim / 128), 256>>>(qkv, ekey, eb);
        attn_kernel<<<BHdim, 256, ATT_BYTES>>>(qkv, eb, mask, at, ctx);
        ev_kernel<<<dim3(Sdim, BHdim / 128), 256, EV_BYTES>>>(at, evalp, ctx);

        mma_gemm<false><<<dim3(Ddim / 128, NR / 128), 256, GSM_BYTES>>>(
            ctx, woT + (size_t)l * Ddim * Ddim, bo + l * Ddim, tmp,
            NR, Ddim, Ddim);
        ln_kernel<<<NR / 8, 256>>>(tmp, x, 1.f, ln1g + l * Ddim, ln1b + l * Ddim, x);

        mma_gemm<true><<<dim3(Fdim / 128, NR / 128), 256, GSM_BYTES>>>(
            x, w1T + (size_t)l * Fdim * Ddim, b1 + l * Fdim, ff,
            NR, Fdim, Ddim);
        mma_gemm<false><<<dim3(Ddim / 128, NR / 128), 256, GSM_BYTES>>>(
            ff, w2T + (size_t)l * Ddim * Fdim, b2 + l * Ddim, tmp,
            NR, Ddim, Fdim);
        ln_kernel<<<NR / 8, 256>>>(tmp, nullptr, 2.f, ln2g + l * Ddim, ln2b + l * Ddim, x);
    }

    out_transpose<<<NR * Ddim / 256, 256>>>(x, (float*)d_out);
}